// round 3
// baseline (speedup 1.0000x reference)
#include <cuda_runtime.h>
#include <cuda_bf16.h>
#include <math.h>

// ---------------------------------------------------------------------------
// Problem constants
// ---------------------------------------------------------------------------
#define BATCH   2
#define SEQ     2048
#define CDIM    2048
#define HEADS   16
#define DHEAD   128
#define LDIM    512
#define MROWS   (BATCH * SEQ)   // 4096

// ---------------------------------------------------------------------------
// Scratch (device globals: allocation-free at kernel_launch time)
// ---------------------------------------------------------------------------
__device__ float g_kvd [MROWS * LDIM];        // kv_d            [4096, 512]
__device__ float g_qd  [MROWS * LDIM];        // q_d             [4096, 512]
__device__ float g_t1  [MROWS * (CDIM/2)];    // k_c / q_c       [4096, 1024]
__device__ float g_t2  [MROWS * (CDIM/2)];    // k_r / q_r pre   [4096, 1024]
__device__ float g_k   [MROWS * CDIM];        // assembled K     [4096, 2048]
__device__ float g_q   [MROWS * CDIM];        // assembled Q     [4096, 2048]
__device__ float g_v   [MROWS * CDIM];        // V               [4096, 2048]
__device__ float g_attn[MROWS * CDIM];        // attention out   [4096, 2048]

// ---------------------------------------------------------------------------
// GEMM:  C[M,N] = A[M,K] @ W[N,K]^T      (both operands K-contiguous, NT)
// 128x128 block tile, BK=8, 256 threads, 8x8 micro-tile in 4x4 quadrants.
// Requires M%128==0, N%128==0, K%8==0 (true for all call sites).
// ---------------------------------------------------------------------------
__global__ void __launch_bounds__(256, 2)
gemm_nt_kernel(const float* __restrict__ A, const float* __restrict__ W,
               float* __restrict__ C, int M, int N, int K)
{
    __shared__ float As[8][128];   // [k][m]
    __shared__ float Ws[8][128];   // [k][n]

    const int tid  = threadIdx.x;
    const int tx   = tid & 15;
    const int ty   = tid >> 4;
    const int lrow = tid >> 1;          // 0..127
    const int lk   = (tid & 1) * 4;     // 0 or 4

    const float* Ap = A + (size_t)(blockIdx.y * 128 + lrow) * K + lk;
    const float* Wp = W + (size_t)(blockIdx.x * 128 + lrow) * K + lk;

    float acc[8][8];
#pragma unroll
    for (int i = 0; i < 8; i++)
#pragma unroll
        for (int j = 0; j < 8; j++) acc[i][j] = 0.0f;

    for (int k0 = 0; k0 < K; k0 += 8) {
        const float4 av = *(const float4*)(Ap + k0);
        const float4 wv = *(const float4*)(Wp + k0);
        __syncthreads();
        As[lk + 0][lrow] = av.x; As[lk + 1][lrow] = av.y;
        As[lk + 2][lrow] = av.z; As[lk + 3][lrow] = av.w;
        Ws[lk + 0][lrow] = wv.x; Ws[lk + 1][lrow] = wv.y;
        Ws[lk + 2][lrow] = wv.z; Ws[lk + 3][lrow] = wv.w;
        __syncthreads();
#pragma unroll
        for (int kk = 0; kk < 8; kk++) {
            const float4 a0 = *(const float4*)&As[kk][ty * 4];
            const float4 a1 = *(const float4*)&As[kk][64 + ty * 4];
            const float4 b0 = *(const float4*)&Ws[kk][tx * 4];
            const float4 b1 = *(const float4*)&Ws[kk][64 + tx * 4];
            const float a[8] = {a0.x, a0.y, a0.z, a0.w, a1.x, a1.y, a1.z, a1.w};
            const float b[8] = {b0.x, b0.y, b0.z, b0.w, b1.x, b1.y, b1.z, b1.w};
#pragma unroll
            for (int i = 0; i < 8; i++)
#pragma unroll
                for (int j = 0; j < 8; j++)
                    acc[i][j] = fmaf(a[i], b[j], acc[i][j]);
        }
    }

    const int rb = blockIdx.y * 128;
    const int cb = blockIdx.x * 128;
#pragma unroll
    for (int i = 0; i < 8; i++) {
        const int r = rb + ((i < 4) ? (ty * 4 + i) : (64 + ty * 4 + i - 4));
        float* Cp = C + (size_t)r * N + cb;
        *(float4*)&Cp[tx * 4]      = make_float4(acc[i][0], acc[i][1], acc[i][2], acc[i][3]);
        *(float4*)&Cp[64 + tx * 4] = make_float4(acc[i][4], acc[i][5], acc[i][6], acc[i][7]);
    }
}

// ---------------------------------------------------------------------------
// RoPE (interleaved) + head-concat assembly.
//   cpart : [4096, 1024]  (k_c or q_c)         -> out[.., h*128 + d],   d<64
//   rpre  : [4096, 1024]  (pre-rope k_r / q_r) -> out[.., h*128+64+d],  d<64
// One block per row, 512 threads = 512 (even,odd) pairs.
// ---------------------------------------------------------------------------
__global__ void __launch_bounds__(512)
assemble_rope_kernel(const float* __restrict__ cpart,
                     const float* __restrict__ rpre,
                     float* __restrict__ out)
{
    const int row = blockIdx.x;          // 0..4095
    const int p   = threadIdx.x;         // 0..511 (pair index)
    const int t   = row & (SEQ - 1);     // position within sequence

    // freq = exp(2p * (-ln(10000)/1024)),  D = 1024
    const float freq = expf((float)(2 * p) * (-9.210340371976184f / 1024.0f));
    const float ang  = (float)t * freq;
    float s, c;
    sincosf(ang, &s, &c);

    const float xe = rpre[(size_t)row * 1024 + 2 * p];
    const float xo = rpre[(size_t)row * 1024 + 2 * p + 1];
    const float re = xe * c - xo * s;
    const float ro = xo * c + xe * s;

    const int h  = p >> 5;               // (2p)/64
    const int d0 = (2 * p) & 63;
    float* o = out + (size_t)row * CDIM + h * DHEAD;
    o[64 + d0]     = re;
    o[64 + d0 + 1] = ro;
    o[d0]          = cpart[(size_t)row * 1024 + 2 * p];
    o[d0 + 1]      = cpart[(size_t)row * 1024 + 2 * p + 1];
}

// ---------------------------------------------------------------------------
// Causal flash attention, fp32. Q/K/V/O layout: [4096, H*128] (= B,T,H,DH).
// Block = (q-tile of 64) x (b,h). 256 threads, 4x4 score micro-tile,
// online softmax, P staged via smem for the PV GEMM.
// ---------------------------------------------------------------------------
#define FLASH_SMEM_BYTES ((128*64 + 128*64 + 64*128 + 64*64) * 4)  // 114688

__global__ void __launch_bounds__(256)
flash_kernel(const float* __restrict__ Q, const float* __restrict__ Kg,
             const float* __restrict__ V, float* __restrict__ O)
{
    extern __shared__ float sm[];
    float* q_s = sm;             // [kd][row] 128x64 (transposed, scale folded)
    float* k_s = sm + 8192;      // [kd][row] 128x64 (transposed)
    float* v_s = sm + 16384;     // [row][c]  64x128
    float* p_s = sm + 24576;     // [r][k]    64x64

    const int tid = threadIdx.x;
    const int tx  = tid & 15;
    const int ty  = tid >> 4;
    const int qt  = blockIdx.x;
    const int b   = blockIdx.y >> 4;
    const int h   = blockIdx.y & 15;
    const int q0  = qt * 64;
    const float scale = 0.08838834764831845f;   // 1/sqrt(128)

    // Load Q tile (transposed into smem, scale folded in)
    const float* Qbase = Q + (size_t)(b * SEQ + q0) * CDIM + h * DHEAD;
#pragma unroll
    for (int it = 0; it < 8; it++) {
        const int idx = tid + it * 256;          // 0..2047
        const int r   = idx >> 5;
        const int c4  = (idx & 31) << 2;
        const float4 qv = *(const float4*)(Qbase + (size_t)r * CDIM + c4);
        q_s[(c4 + 0) * 64 + r] = qv.x * scale;
        q_s[(c4 + 1) * 64 + r] = qv.y * scale;
        q_s[(c4 + 2) * 64 + r] = qv.z * scale;
        q_s[(c4 + 3) * 64 + r] = qv.w * scale;
    }

    float m_i[4] = {-INFINITY, -INFINITY, -INFINITY, -INFINITY};
    float l_i[4] = {0.f, 0.f, 0.f, 0.f};
    float o_acc[4][8];
#pragma unroll
    for (int i = 0; i < 4; i++)
#pragma unroll
        for (int c = 0; c < 8; c++) o_acc[i][c] = 0.f;

    for (int j = 0; j <= qt; j++) {
        const int k0 = j * 64;
        const float* Kbase = Kg + (size_t)(b * SEQ + k0) * CDIM + h * DHEAD;
        const float* Vbase = V  + (size_t)(b * SEQ + k0) * CDIM + h * DHEAD;

        __syncthreads();   // previous PV done (also covers Q-store on j==0)
#pragma unroll
        for (int it = 0; it < 8; it++) {
            const int idx = tid + it * 256;
            const int r   = idx >> 5;
            const int c4  = (idx & 31) << 2;
            const float4 kv = *(const float4*)(Kbase + (size_t)r * CDIM + c4);
            k_s[(c4 + 0) * 64 + r] = kv.x;
            k_s[(c4 + 1) * 64 + r] = kv.y;
            k_s[(c4 + 2) * 64 + r] = kv.z;
            k_s[(c4 + 3) * 64 + r] = kv.w;
            const float4 vv = *(const float4*)(Vbase + (size_t)r * CDIM + c4);
            *(float4*)&v_s[r * 128 + c4] = vv;
        }
        __syncthreads();

        // S = (Q*scale) . K^T   (4x4 per thread)
        float s[4][4] = {{0.f,0.f,0.f,0.f},{0.f,0.f,0.f,0.f},
                         {0.f,0.f,0.f,0.f},{0.f,0.f,0.f,0.f}};
#pragma unroll 8
        for (int kd = 0; kd < 128; kd++) {
            const float4 qa = *(const float4*)&q_s[kd * 64 + ty * 4];
            const float4 kb = *(const float4*)&k_s[kd * 64 + tx * 4];
            s[0][0] = fmaf(qa.x, kb.x, s[0][0]); s[0][1] = fmaf(qa.x, kb.y, s[0][1]);
            s[0][2] = fmaf(qa.x, kb.z, s[0][2]); s[0][3] = fmaf(qa.x, kb.w, s[0][3]);
            s[1][0] = fmaf(qa.y, kb.x, s[1][0]); s[1][1] = fmaf(qa.y, kb.y, s[1][1]);
            s[1][2] = fmaf(qa.y, kb.z, s[1][2]); s[1][3] = fmaf(qa.y, kb.w, s[1][3]);
            s[2][0] = fmaf(qa.z, kb.x, s[2][0]); s[2][1] = fmaf(qa.z, kb.y, s[2][1]);
            s[2][2] = fmaf(qa.z, kb.z, s[2][2]); s[2][3] = fmaf(qa.z, kb.w, s[2][3]);
            s[3][0] = fmaf(qa.w, kb.x, s[3][0]); s[3][1] = fmaf(qa.w, kb.y, s[3][1]);
            s[3][2] = fmaf(qa.w, kb.z, s[3][2]); s[3][3] = fmaf(qa.w, kb.w, s[3][3]);
        }

        if (j == qt) {   // diagonal tile: causal mask
#pragma unroll
            for (int i = 0; i < 4; i++)
#pragma unroll
                for (int jj = 0; jj < 4; jj++)
                    if (k0 + tx * 4 + jj > q0 + ty * 4 + i) s[i][jj] = -INFINITY;
        }

        // online softmax per row (rows replicated across 16 tx lanes)
#pragma unroll
        for (int i = 0; i < 4; i++) {
            float mt = fmaxf(fmaxf(s[i][0], s[i][1]), fmaxf(s[i][2], s[i][3]));
            mt = fmaxf(mt, __shfl_xor_sync(0xffffffffu, mt, 1));
            mt = fmaxf(mt, __shfl_xor_sync(0xffffffffu, mt, 2));
            mt = fmaxf(mt, __shfl_xor_sync(0xffffffffu, mt, 4));
            mt = fmaxf(mt, __shfl_xor_sync(0xffffffffu, mt, 8));
            const float m_new = fmaxf(m_i[i], mt);
            const float alpha = expf(m_i[i] - m_new);   // 0 if m_i == -inf
            float rs = 0.f;
#pragma unroll
            for (int jj = 0; jj < 4; jj++) {
                const float p = expf(s[i][jj] - m_new);
                s[i][jj] = p;
                rs += p;
            }
            rs += __shfl_xor_sync(0xffffffffu, rs, 1);
            rs += __shfl_xor_sync(0xffffffffu, rs, 2);
            rs += __shfl_xor_sync(0xffffffffu, rs, 4);
            rs += __shfl_xor_sync(0xffffffffu, rs, 8);
            l_i[i] = alpha * l_i[i] + rs;
            m_i[i] = m_new;
#pragma unroll
            for (int c = 0; c < 8; c++) o_acc[i][c] *= alpha;
            *(float4*)&p_s[(ty * 4 + i) * 64 + tx * 4] =
                make_float4(s[i][0], s[i][1], s[i][2], s[i][3]);
        }
        __syncthreads();

        // O += P . V
#pragma unroll 4
        for (int kk = 0; kk < 64; kk++) {
            const float4 v0 = *(const float4*)&v_s[kk * 128 + tx * 4];
            const float4 v1 = *(const float4*)&v_s[kk * 128 + 64 + tx * 4];
#pragma unroll
            for (int i = 0; i < 4; i++) {
                const float pp = p_s[(ty * 4 + i) * 64 + kk];
                o_acc[i][0] = fmaf(pp, v0.x, o_acc[i][0]);
                o_acc[i][1] = fmaf(pp, v0.y, o_acc[i][1]);
                o_acc[i][2] = fmaf(pp, v0.z, o_acc[i][2]);
                o_acc[i][3] = fmaf(pp, v0.w, o_acc[i][3]);
                o_acc[i][4] = fmaf(pp, v1.x, o_acc[i][4]);
                o_acc[i][5] = fmaf(pp, v1.y, o_acc[i][5]);
                o_acc[i][6] = fmaf(pp, v1.z, o_acc[i][6]);
                o_acc[i][7] = fmaf(pp, v1.w, o_acc[i][7]);
            }
        }
    }

    // epilogue: divide by l, store
    float* Obase = O + (size_t)(b * SEQ + q0) * CDIM + h * DHEAD;
#pragma unroll
    for (int i = 0; i < 4; i++) {
        const float inv = 1.0f / l_i[i];
        const int r = ty * 4 + i;
        *(float4*)(Obase + (size_t)r * CDIM + tx * 4) =
            make_float4(o_acc[i][0] * inv, o_acc[i][1] * inv,
                        o_acc[i][2] * inv, o_acc[i][3] * inv);
        *(float4*)(Obase + (size_t)r * CDIM + 64 + tx * 4) =
            make_float4(o_acc[i][4] * inv, o_acc[i][5] * inv,
                        o_acc[i][6] * inv, o_acc[i][7] * inv);
    }
}

// ---------------------------------------------------------------------------
// Launch
// ---------------------------------------------------------------------------
static void launch_gemm(const float* A, const float* W, float* C,
                        int M, int N, int K)
{
    dim3 grid(N / 128, M / 128);
    gemm_nt_kernel<<<grid, 256>>>(A, W, C, M, N, K);
}

extern "C" void kernel_launch(void* const* d_in, const int* in_sizes, int n_in,
                              void* d_out, int out_size)
{
    (void)in_sizes; (void)n_in; (void)out_size;
    const float* x     = (const float*)d_in[0];
    const float* W_kvD = (const float*)d_in[1];
    const float* W_qD  = (const float*)d_in[2];
    const float* W_kU  = (const float*)d_in[3];
    const float* W_vU  = (const float*)d_in[4];
    const float* W_qU  = (const float*)d_in[5];
    const float* W_rk  = (const float*)d_in[6];
    const float* W_rq  = (const float*)d_in[7];
    const float* W_o   = (const float*)d_in[8];
    float* out = (float*)d_out;

    float *kvd, *qd, *t1, *t2, *kb, *qb, *vb, *attn;
    cudaGetSymbolAddress((void**)&kvd,  g_kvd);
    cudaGetSymbolAddress((void**)&qd,   g_qd);
    cudaGetSymbolAddress((void**)&t1,   g_t1);
    cudaGetSymbolAddress((void**)&t2,   g_t2);
    cudaGetSymbolAddress((void**)&kb,   g_k);
    cudaGetSymbolAddress((void**)&qb,   g_q);
    cudaGetSymbolAddress((void**)&vb,   g_v);
    cudaGetSymbolAddress((void**)&attn, g_attn);

    // Down-projections
    launch_gemm(x,   W_kvD, kvd, MROWS, LDIM, CDIM);     // kv_d
    launch_gemm(x,   W_qD,  qd,  MROWS, LDIM, CDIM);     // q_d

    // K path
    launch_gemm(kvd, W_kU,  t1,  MROWS, CDIM / 2, LDIM); // k_c
    launch_gemm(x,   W_rk,  t2,  MROWS, CDIM / 2, CDIM); // k_r (pre-rope)
    assemble_rope_kernel<<<MROWS, 512>>>(t1, t2, kb);

    // Q path
    launch_gemm(qd,  W_qU,  t1,  MROWS, CDIM / 2, LDIM); // q_c
    launch_gemm(qd,  W_rq,  t2,  MROWS, CDIM / 2, LDIM); // q_r (pre-rope)
    assemble_rope_kernel<<<MROWS, 512>>>(t1, t2, qb);

    // V
    launch_gemm(kvd, W_vU,  vb,  MROWS, CDIM, LDIM);

    // Attention
    cudaFuncSetAttribute(flash_kernel,
                         cudaFuncAttributeMaxDynamicSharedMemorySize,
                         FLASH_SMEM_BYTES);
    flash_kernel<<<dim3(SEQ / 64, BATCH * HEADS), 256, FLASH_SMEM_BYTES>>>(
        qb, kb, vb, attn);

    // Output projection
    launch_gemm(attn, W_o, out, MROWS, CDIM, CDIM);
}

// round 6
// speedup vs baseline: 1.2718x; 1.2718x over previous
#include <cuda_runtime.h>
#include <cuda_bf16.h>
#include <math.h>
#include <stdint.h>

// ---------------------------------------------------------------------------
// Problem constants
// ---------------------------------------------------------------------------
#define BATCH   2
#define SEQ     2048
#define CDIM    2048
#define HEADS   16
#define DHEAD   128
#define LDIM    512
#define MROWS   (BATCH * SEQ)   // 4096

// ---------------------------------------------------------------------------
// Scratch (device globals: allocation-free at kernel_launch time)
// ---------------------------------------------------------------------------
__device__ float g_kvd [MROWS * LDIM];
__device__ float g_qd  [MROWS * LDIM];
__device__ float g_t1  [MROWS * (CDIM/2)];
__device__ float g_t2  [MROWS * (CDIM/2)];
__device__ float g_k   [MROWS * CDIM];
__device__ float g_q   [MROWS * CDIM];
__device__ float g_v   [MROWS * CDIM];
__device__ float g_attn[MROWS * CDIM];

// ---------------------------------------------------------------------------
// tf32 helpers (sm_80+ ISA only — NO tcgen05; ptxas here targets plain sm_100)
// ---------------------------------------------------------------------------
__device__ __forceinline__ uint32_t f2tf32(float x) {
    uint32_t r;
    asm("cvt.rna.tf32.f32 %0, %1;" : "=r"(r) : "f"(x));
    return r;
}

// D(16x8) += A(16x8) * B(8x8), tf32 inputs (as .b32), fp32 accumulators.
#define MMA_TF32(d, a, b)                                                     \
    asm volatile("mma.sync.aligned.m16n8k8.row.col.f32.tf32.tf32.f32 "        \
                 "{%0,%1,%2,%3}, {%4,%5,%6,%7}, {%8,%9}, {%0,%1,%2,%3};"      \
                 : "+f"((d)[0]), "+f"((d)[1]), "+f"((d)[2]), "+f"((d)[3])     \
                 : "r"((a)[0]), "r"((a)[1]), "r"((a)[2]), "r"((a)[3]),        \
                   "r"((b)[0]), "r"((b)[1]))

// ---------------------------------------------------------------------------
// Tensor-core tf32 GEMM:  C[M,N] = A[M,K] @ W[N,K]^T
// 128x128 block tile, BK=32, 256 threads = 8 warps in 2(m)x4(n) grid,
// warp tile 64x32. Operands staged k-major ([k][row], pad 132 words) with
// cvt.rna.tf32 at staging. Double-buffered smem, LDG pipelined 2 chunks ahead.
// Fragment map (m16n8k8, lane = 4g+t, g=lane>>2, t=lane&3):
//   A: a0=(g,t) a1=(g+8,t) a2=(g,t+4) a3=(g+8,t+4)   [rows m, cols k]
//   B: b0=(t,g) b1=(t+4,g)                            [rows k, cols n]
//   C: c0=(g,2t) c1=(g,2t+1) c2=(g+8,2t) c3=(g+8,2t+1)
// smem LDS banks: (k*132 + r) % 32 = (4t + g) % 32 -> conflict-free.
// ---------------------------------------------------------------------------
#define BK      32
#define PADW    132                       // words per k-row (128 + 4)
#define TILEW   (BK * PADW)               // 4224 words per tile
#define GT_SMEM (4 * TILEW * 4)           // 2 buffers x (A + B) = 67584 bytes

__global__ void __launch_bounds__(256, 1)
gemm_tf32_kernel(const float* __restrict__ A, const float* __restrict__ W,
                 float* __restrict__ C, int M, int N, int K)
{
    extern __shared__ uint32_t smem[];
    uint32_t* bufA[2] = { smem,             smem + 2 * TILEW };
    uint32_t* bufB[2] = { smem + TILEW,     smem + 3 * TILEW };

    const int tid  = threadIdx.x;
    const int wid  = tid >> 5;
    const int lane = tid & 31;
    const int g    = lane >> 2;
    const int t    = lane & 3;
    const int wm   = (wid >> 2) * 64;     // 0 | 64
    const int wn   = (wid & 3) * 32;      // 0 | 32 | 64 | 96

    // global staging assignment: 2 threads per row, 4 float4 each
    const int lr = tid >> 1;              // 0..127
    const int lk = (tid & 1) * 16;        // k base 0 | 16
    const float* Ap = A + (size_t)(blockIdx.y * 128 + lr) * K + lk;
    const float* Wp = W + (size_t)(blockIdx.x * 128 + lr) * K + lk;

    float4 ra[4], rw[4];

#define LDG_CHUNK(i)                                                          \
    do {                                                                      \
        const float* _a = Ap + (i) * BK;                                      \
        const float* _w = Wp + (i) * BK;                                      \
        _Pragma("unroll")                                                     \
        for (int j = 0; j < 4; j++) {                                         \
            ra[j] = *(const float4*)(_a + 4 * j);                             \
            rw[j] = *(const float4*)(_w + 4 * j);                             \
        }                                                                     \
    } while (0)

#define STS_CHUNK(buf)                                                        \
    do {                                                                      \
        uint32_t* _as = bufA[buf];                                            \
        uint32_t* _bs = bufB[buf];                                            \
        _Pragma("unroll")                                                     \
        for (int j = 0; j < 4; j++) {                                         \
            const int k = lk + 4 * j;                                         \
            _as[(k + 0) * PADW + lr] = f2tf32(ra[j].x);                       \
            _as[(k + 1) * PADW + lr] = f2tf32(ra[j].y);                       \
            _as[(k + 2) * PADW + lr] = f2tf32(ra[j].z);                       \
            _as[(k + 3) * PADW + lr] = f2tf32(ra[j].w);                       \
            _bs[(k + 0) * PADW + lr] = f2tf32(rw[j].x);                       \
            _bs[(k + 1) * PADW + lr] = f2tf32(rw[j].y);                       \
            _bs[(k + 2) * PADW + lr] = f2tf32(rw[j].z);                       \
            _bs[(k + 3) * PADW + lr] = f2tf32(rw[j].w);                       \
        }                                                                     \
    } while (0)

    float acc[4][4][4];
#pragma unroll
    for (int mt = 0; mt < 4; mt++)
#pragma unroll
        for (int nt = 0; nt < 4; nt++)
#pragma unroll
            for (int r = 0; r < 4; r++) acc[mt][nt][r] = 0.0f;

    const int nch = K >> 5;

    // prologue
    LDG_CHUNK(0);
    STS_CHUNK(0);
    LDG_CHUNK(1);                         // nch >= 2 at every call site
    __syncthreads();

    for (int i = 0; i < nch; i++) {
        const int cur = i & 1;
        const uint32_t* as = bufA[cur];
        const uint32_t* bs = bufB[cur];

#pragma unroll
        for (int ks = 0; ks < 4; ks++) {
            const uint32_t* a0p = as + (ks * 8 + t) * PADW;
            const uint32_t* a4p = as + (ks * 8 + t + 4) * PADW;
            const uint32_t* b0p = bs + (ks * 8 + t) * PADW;
            const uint32_t* b4p = bs + (ks * 8 + t + 4) * PADW;

            uint32_t afr[4][4], bfr[4][2];
#pragma unroll
            for (int mt = 0; mt < 4; mt++) {
                const int r = wm + mt * 16 + g;
                afr[mt][0] = a0p[r];     afr[mt][1] = a0p[r + 8];
                afr[mt][2] = a4p[r];     afr[mt][3] = a4p[r + 8];
            }
#pragma unroll
            for (int nt = 0; nt < 4; nt++) {
                const int c = wn + nt * 8 + g;
                bfr[nt][0] = b0p[c];     bfr[nt][1] = b4p[c];
            }
#pragma unroll
            for (int mt = 0; mt < 4; mt++)
#pragma unroll
                for (int nt = 0; nt < 4; nt++)
                    MMA_TF32(acc[mt][nt], afr[mt], bfr[nt]);
        }

        if (i + 1 < nch) {
            STS_CHUNK(cur ^ 1);
            if (i + 2 < nch) LDG_CHUNK(i + 2);
            __syncthreads();
        }
    }

    // epilogue: direct fp32 stores (float2 per c-pair, 8B aligned)
    const int rowb = blockIdx.y * 128 + wm;
    const int colb = blockIdx.x * 128 + wn;
#pragma unroll
    for (int mt = 0; mt < 4; mt++) {
        const int r0 = rowb + mt * 16 + g;
#pragma unroll
        for (int nt = 0; nt < 4; nt++) {
            float* Cp = C + (size_t)r0 * N + colb + nt * 8 + 2 * t;
            *(float2*)Cp                 = make_float2(acc[mt][nt][0], acc[mt][nt][1]);
            *(float2*)(Cp + (size_t)8 * N) = make_float2(acc[mt][nt][2], acc[mt][nt][3]);
        }
    }
#undef LDG_CHUNK
#undef STS_CHUNK
}

// ---------------------------------------------------------------------------
// RoPE (interleaved) + head-concat assembly.  (unchanged)
// ---------------------------------------------------------------------------
__global__ void __launch_bounds__(512)
assemble_rope_kernel(const float* __restrict__ cpart,
                     const float* __restrict__ rpre,
                     float* __restrict__ out)
{
    const int row = blockIdx.x;
    const int p   = threadIdx.x;
    const int t   = row & (SEQ - 1);

    const float freq = expf((float)(2 * p) * (-9.210340371976184f / 1024.0f));
    const float ang  = (float)t * freq;
    float s, c;
    sincosf(ang, &s, &c);

    const float xe = rpre[(size_t)row * 1024 + 2 * p];
    const float xo = rpre[(size_t)row * 1024 + 2 * p + 1];
    const float re = xe * c - xo * s;
    const float ro = xo * c + xe * s;

    const int h  = p >> 5;
    const int d0 = (2 * p) & 63;
    float* o = out + (size_t)row * CDIM + h * DHEAD;
    o[64 + d0]     = re;
    o[64 + d0 + 1] = ro;
    o[d0]          = cpart[(size_t)row * 1024 + 2 * p];
    o[d0 + 1]      = cpart[(size_t)row * 1024 + 2 * p + 1];
}

// ---------------------------------------------------------------------------
// Causal flash attention, fp32.  (unchanged — R6 target)
// ---------------------------------------------------------------------------
#define FLASH_SMEM_BYTES ((128*64 + 128*64 + 64*128 + 64*64) * 4)  // 114688

__global__ void __launch_bounds__(256)
flash_kernel(const float* __restrict__ Q, const float* __restrict__ Kg,
             const float* __restrict__ V, float* __restrict__ O)
{
    extern __shared__ float fsm[];
    float* q_s = fsm;
    float* k_s = fsm + 8192;
    float* v_s = fsm + 16384;
    float* p_s = fsm + 24576;

    const int tid = threadIdx.x;
    const int tx  = tid & 15;
    const int ty  = tid >> 4;
    const int qt  = blockIdx.x;
    const int b   = blockIdx.y >> 4;
    const int h   = blockIdx.y & 15;
    const int q0  = qt * 64;
    const float scale = 0.08838834764831845f;

    const float* Qbase = Q + (size_t)(b * SEQ + q0) * CDIM + h * DHEAD;
#pragma unroll
    for (int it = 0; it < 8; it++) {
        const int idx = tid + it * 256;
        const int r   = idx >> 5;
        const int c4  = (idx & 31) << 2;
        const float4 qv = *(const float4*)(Qbase + (size_t)r * CDIM + c4);
        q_s[(c4 + 0) * 64 + r] = qv.x * scale;
        q_s[(c4 + 1) * 64 + r] = qv.y * scale;
        q_s[(c4 + 2) * 64 + r] = qv.z * scale;
        q_s[(c4 + 3) * 64 + r] = qv.w * scale;
    }

    float m_i[4] = {-INFINITY, -INFINITY, -INFINITY, -INFINITY};
    float l_i[4] = {0.f, 0.f, 0.f, 0.f};
    float o_acc[4][8];
#pragma unroll
    for (int i = 0; i < 4; i++)
#pragma unroll
        for (int c = 0; c < 8; c++) o_acc[i][c] = 0.f;

    for (int j = 0; j <= qt; j++) {
        const int k0 = j * 64;
        const float* Kbase = Kg + (size_t)(b * SEQ + k0) * CDIM + h * DHEAD;
        const float* Vbase = V  + (size_t)(b * SEQ + k0) * CDIM + h * DHEAD;

        __syncthreads();
#pragma unroll
        for (int it = 0; it < 8; it++) {
            const int idx = tid + it * 256;
            const int r   = idx >> 5;
            const int c4  = (idx & 31) << 2;
            const float4 kv = *(const float4*)(Kbase + (size_t)r * CDIM + c4);
            k_s[(c4 + 0) * 64 + r] = kv.x;
            k_s[(c4 + 1) * 64 + r] = kv.y;
            k_s[(c4 + 2) * 64 + r] = kv.z;
            k_s[(c4 + 3) * 64 + r] = kv.w;
            const float4 vv = *(const float4*)(Vbase + (size_t)r * CDIM + c4);
            *(float4*)&v_s[r * 128 + c4] = vv;
        }
        __syncthreads();

        float s[4][4] = {{0.f,0.f,0.f,0.f},{0.f,0.f,0.f,0.f},
                         {0.f,0.f,0.f,0.f},{0.f,0.f,0.f,0.f}};
#pragma unroll 8
        for (int kd = 0; kd < 128; kd++) {
            const float4 qa = *(const float4*)&q_s[kd * 64 + ty * 4];
            const float4 kb = *(const float4*)&k_s[kd * 64 + tx * 4];
            s[0][0] = fmaf(qa.x, kb.x, s[0][0]); s[0][1] = fmaf(qa.x, kb.y, s[0][1]);
            s[0][2] = fmaf(qa.x, kb.z, s[0][2]); s[0][3] = fmaf(qa.x, kb.w, s[0][3]);
            s[1][0] = fmaf(qa.y, kb.x, s[1][0]); s[1][1] = fmaf(qa.y, kb.y, s[1][1]);
            s[1][2] = fmaf(qa.y, kb.z, s[1][2]); s[1][3] = fmaf(qa.y, kb.w, s[1][3]);
            s[2][0] = fmaf(qa.z, kb.x, s[2][0]); s[2][1] = fmaf(qa.z, kb.y, s[2][1]);
            s[2][2] = fmaf(qa.z, kb.z, s[2][2]); s[2][3] = fmaf(qa.z, kb.w, s[2][3]);
            s[3][0] = fmaf(qa.w, kb.x, s[3][0]); s[3][1] = fmaf(qa.w, kb.y, s[3][1]);
            s[3][2] = fmaf(qa.w, kb.z, s[3][2]); s[3][3] = fmaf(qa.w, kb.w, s[3][3]);
        }

        if (j == qt) {
#pragma unroll
            for (int i = 0; i < 4; i++)
#pragma unroll
                for (int jj = 0; jj < 4; jj++)
                    if (k0 + tx * 4 + jj > q0 + ty * 4 + i) s[i][jj] = -INFINITY;
        }

#pragma unroll
        for (int i = 0; i < 4; i++) {
            float mt = fmaxf(fmaxf(s[i][0], s[i][1]), fmaxf(s[i][2], s[i][3]));
            mt = fmaxf(mt, __shfl_xor_sync(0xffffffffu, mt, 1));
            mt = fmaxf(mt, __shfl_xor_sync(0xffffffffu, mt, 2));
            mt = fmaxf(mt, __shfl_xor_sync(0xffffffffu, mt, 4));
            mt = fmaxf(mt, __shfl_xor_sync(0xffffffffu, mt, 8));
            const float m_new = fmaxf(m_i[i], mt);
            const float alpha = expf(m_i[i] - m_new);
            float rs = 0.f;
#pragma unroll
            for (int jj = 0; jj < 4; jj++) {
                const float p = expf(s[i][jj] - m_new);
                s[i][jj] = p;
                rs += p;
            }
            rs += __shfl_xor_sync(0xffffffffu, rs, 1);
            rs += __shfl_xor_sync(0xffffffffu, rs, 2);
            rs += __shfl_xor_sync(0xffffffffu, rs, 4);
            rs += __shfl_xor_sync(0xffffffffu, rs, 8);
            l_i[i] = alpha * l_i[i] + rs;
            m_i[i] = m_new;
#pragma unroll
            for (int c = 0; c < 8; c++) o_acc[i][c] *= alpha;
            *(float4*)&p_s[(ty * 4 + i) * 64 + tx * 4] =
                make_float4(s[i][0], s[i][1], s[i][2], s[i][3]);
        }
        __syncthreads();

#pragma unroll 4
        for (int kk = 0; kk < 64; kk++) {
            const float4 v0 = *(const float4*)&v_s[kk * 128 + tx * 4];
            const float4 v1 = *(const float4*)&v_s[kk * 128 + 64 + tx * 4];
#pragma unroll
            for (int i = 0; i < 4; i++) {
                const float pp = p_s[(ty * 4 + i) * 64 + kk];
                o_acc[i][0] = fmaf(pp, v0.x, o_acc[i][0]);
                o_acc[i][1] = fmaf(pp, v0.y, o_acc[i][1]);
                o_acc[i][2] = fmaf(pp, v0.z, o_acc[i][2]);
                o_acc[i][3] = fmaf(pp, v0.w, o_acc[i][3]);
                o_acc[i][4] = fmaf(pp, v1.x, o_acc[i][4]);
                o_acc[i][5] = fmaf(pp, v1.y, o_acc[i][5]);
                o_acc[i][6] = fmaf(pp, v1.z, o_acc[i][6]);
                o_acc[i][7] = fmaf(pp, v1.w, o_acc[i][7]);
            }
        }
    }

    float* Obase = O + (size_t)(b * SEQ + q0) * CDIM + h * DHEAD;
#pragma unroll
    for (int i = 0; i < 4; i++) {
        const float inv = 1.0f / l_i[i];
        const int r = ty * 4 + i;
        *(float4*)(Obase + (size_t)r * CDIM + tx * 4) =
            make_float4(o_acc[i][0] * inv, o_acc[i][1] * inv,
                        o_acc[i][2] * inv, o_acc[i][3] * inv);
        *(float4*)(Obase + (size_t)r * CDIM + 64 + tx * 4) =
            make_float4(o_acc[i][4] * inv, o_acc[i][5] * inv,
                        o_acc[i][6] * inv, o_acc[i][7] * inv);
    }
}

// ---------------------------------------------------------------------------
// Launch
// ---------------------------------------------------------------------------
static void launch_gemm(const float* A, const float* W, float* C,
                        int M, int N, int K)
{
    dim3 grid(N / 128, M / 128);
    gemm_tf32_kernel<<<grid, 256, GT_SMEM>>>(A, W, C, M, N, K);
}

extern "C" void kernel_launch(void* const* d_in, const int* in_sizes, int n_in,
                              void* d_out, int out_size)
{
    (void)in_sizes; (void)n_in; (void)out_size;
    const float* x     = (const float*)d_in[0];
    const float* W_kvD = (const float*)d_in[1];
    const float* W_qD  = (const float*)d_in[2];
    const float* W_kU  = (const float*)d_in[3];
    const float* W_vU  = (const float*)d_in[4];
    const float* W_qU  = (const float*)d_in[5];
    const float* W_rk  = (const float*)d_in[6];
    const float* W_rq  = (const float*)d_in[7];
    const float* W_o   = (const float*)d_in[8];
    float* out = (float*)d_out;

    float *kvd, *qd, *t1, *t2, *kb, *qb, *vb, *attn;
    cudaGetSymbolAddress((void**)&kvd,  g_kvd);
    cudaGetSymbolAddress((void**)&qd,   g_qd);
    cudaGetSymbolAddress((void**)&t1,   g_t1);
    cudaGetSymbolAddress((void**)&t2,   g_t2);
    cudaGetSymbolAddress((void**)&kb,   g_k);
    cudaGetSymbolAddress((void**)&qb,   g_q);
    cudaGetSymbolAddress((void**)&vb,   g_v);
    cudaGetSymbolAddress((void**)&attn, g_attn);

    cudaFuncSetAttribute(gemm_tf32_kernel,
                         cudaFuncAttributeMaxDynamicSharedMemorySize, GT_SMEM);
    cudaFuncSetAttribute(flash_kernel,
                         cudaFuncAttributeMaxDynamicSharedMemorySize,
                         FLASH_SMEM_BYTES);

    // Down-projections
    launch_gemm(x,   W_kvD, kvd, MROWS, LDIM, CDIM);
    launch_gemm(x,   W_qD,  qd,  MROWS, LDIM, CDIM);

    // K path
    launch_gemm(kvd, W_kU,  t1,  MROWS, CDIM / 2, LDIM);
    launch_gemm(x,   W_rk,  t2,  MROWS, CDIM / 2, CDIM);
    assemble_rope_kernel<<<MROWS, 512>>>(t1, t2, kb);

    // Q path
    launch_gemm(qd,  W_qU,  t1,  MROWS, CDIM / 2, LDIM);
    launch_gemm(qd,  W_rq,  t2,  MROWS, CDIM / 2, LDIM);
    assemble_rope_kernel<<<MROWS, 512>>>(t1, t2, qb);

    // V
    launch_gemm(kvd, W_vU,  vb,  MROWS, CDIM, LDIM);

    // Attention (fp32 SIMT — R6 target)
    flash_kernel<<<dim3(SEQ / 64, BATCH * HEADS), 256, FLASH_SMEM_BYTES>>>(
        qb, kb, vb, attn);

    // Output projection
    launch_gemm(attn, W_o, out, MROWS, CDIM, CDIM);
}